// round 3
// baseline (speedup 1.0000x reference)
#include <cuda_runtime.h>

// ---------------- problem constants ----------------
#define BB   4
#define NANCH 211200
#define CC   256
#define HH   200
#define WW   176
#define KK   4096

#define BOX_ELEMS (BB * NANCH * 7)          // 5,913,600
#define BEV_ELEMS (BB * CC * KK)            // 4,194,304

// Per-keypoint sample coordinates (ix -> W axis, iy -> H axis), precomputed.
__device__ float2 g_coords[BB * KK];

// ---------------- kernel 1: coordinate precompute ----------------
// Replicates reference math exactly:
//   idx_x = (x - 0)    / (0.05*8)   clipped to [0, W-1]
//   idx_y = (y + 40)   / (0.05*8)   clipped to [0, H-1]
//   nx = 2*idx_x/(W-2) - 1 ; ny = 2*idx_y/(H-2) - 1
//   grid flip => ix = (ny+1)*0.5*(W-1) ; iy = (nx+1)*0.5*(H-1)
__global__ void coords_kernel(const float* __restrict__ kp)
{
    int i = blockIdx.x * blockDim.x + threadIdx.x;
    if (i >= BB * KK) return;

    float x = kp[i * 3 + 0];
    float y = kp[i * 3 + 1];

    const float px = 0.05f * 8.0f;          // base_pixel_size * STRIDE
    float idx_x = (x - 0.0f)    / px;
    float idx_y = (y - (-40.0f)) / px;

    idx_x = fminf(fmaxf(idx_x, 0.0f), (float)(WW - 1));
    idx_y = fminf(fmaxf(idx_y, 0.0f), (float)(HH - 1));

    float nx = 2.0f * (idx_x / (float)(WW - 2)) - 1.0f;
    float ny = 2.0f * (idx_y / (float)(HH - 2)) - 1.0f;

    // grid = flip(indices): grid[...,0] = ny (drives width), grid[...,1] = nx (drives height)
    float ix = (ny + 1.0f) * 0.5f * (float)(WW - 1);
    float iy = (nx + 1.0f) * 0.5f * (float)(HH - 1);

    g_coords[i] = make_float2(ix, iy);
}

// ---------------- kernel 2: box decode ----------------
// One thread per output element. comp = i % 7:
//   0,1 : P * sqrt(Aw^2 + Al^2) + A
//   2   : P * Ah + A
//   3-5 : exp(P) * A
//   6   : P + A
__global__ void decode_kernel(const float* __restrict__ deltas,
                              const float* __restrict__ anchors,
                              float* __restrict__ out)
{
    int i = blockIdx.x * blockDim.x + threadIdx.x;
    if (i >= BOX_ELEMS) return;

    int comp = i % 7;
    int base = i - comp;

    float P = deltas[i];
    float A = anchors[i];
    float r;

    if (comp < 2) {
        float aw = anchors[base + 3];
        float al = anchors[base + 4];
        r = P * sqrtf(aw * aw + al * al) + A;
    } else if (comp == 2) {
        float ah = anchors[base + 5];
        r = P * ah + A;
    } else if (comp < 6) {
        r = expf(P) * A;
    } else {
        r = P + A;
    }
    out[i] = r;
}

// ---------------- kernel 3: BEV bilinear gather ----------------
// One block per (b, c) plane; threads stride over keypoints so the
// out[b][c][k] writes are coalesced and the 140KB plane stays L2-resident.
__global__ void __launch_bounds__(256)
gather_kernel(const float* __restrict__ fm, float* __restrict__ out)
{
    const int c = blockIdx.x;
    const int b = blockIdx.y;

    const float* __restrict__ plane = fm + ((size_t)(b * CC + c)) * (HH * WW);
    float* __restrict__ orow        = out + ((size_t)(b * CC + c)) * KK;
    const float2* __restrict__ coords = g_coords + b * KK;

    #pragma unroll
    for (int t = 0; t < KK / 256; t++) {
        int k = t * 256 + threadIdx.x;
        float2 g = coords[k];

        float x0f = floorf(g.x);
        float y0f = floorf(g.y);
        float wx = g.x - x0f;
        float wy = g.y - y0f;
        int x0 = (int)x0f;
        int y0 = (int)y0f;
        int x1 = x0 + 1;
        int y1 = y0 + 1;

        bool vx0 = (x0 >= 0) && (x0 <= WW - 1);
        bool vx1 = (x1 >= 0) && (x1 <= WW - 1);
        bool vy0 = (y0 >= 0) && (y0 <= HH - 1);
        bool vy1 = (y1 >= 0) && (y1 <= HH - 1);

        int x0c = min(max(x0, 0), WW - 1);
        int x1c = min(max(x1, 0), WW - 1);
        int y0c = min(max(y0, 0), HH - 1);
        int y1c = min(max(y1, 0), HH - 1);

        float v00 = (vx0 && vy0) ? __ldg(plane + y0c * WW + x0c) : 0.0f;
        float v01 = (vx1 && vy0) ? __ldg(plane + y0c * WW + x1c) : 0.0f;
        float v10 = (vx0 && vy1) ? __ldg(plane + y1c * WW + x0c) : 0.0f;
        float v11 = (vx1 && vy1) ? __ldg(plane + y1c * WW + x1c) : 0.0f;

        float r = v00 * (1.0f - wx) * (1.0f - wy)
                + v01 * wx          * (1.0f - wy)
                + v10 * (1.0f - wx) * wy
                + v11 * wx          * wy;

        orow[k] = r;
    }
}

// ---------------- launch ----------------
extern "C" void kernel_launch(void* const* d_in, const int* in_sizes, int n_in,
                              void* d_out, int out_size)
{
    const float* deltas   = (const float*)d_in[0];
    const float* anchors  = (const float*)d_in[1];
    const float* fm       = (const float*)d_in[2];
    const float* kp       = (const float*)d_in[3];

    float* boxes_out = (float*)d_out;
    float* bev_out   = (float*)d_out + BOX_ELEMS;

    // 1. per-keypoint sample coordinates (tiny)
    {
        int n = BB * KK;
        coords_kernel<<<(n + 255) / 256, 256>>>(kp);
    }

    // 2. box decode (pure streaming)
    {
        decode_kernel<<<(BOX_ELEMS + 255) / 256, 256>>>(deltas, anchors, boxes_out);
    }

    // 3. BEV gather: one block per (b, c)
    {
        dim3 grid(CC, BB);
        gather_kernel<<<grid, 256>>>(fm, bev_out);
    }

    (void)in_sizes; (void)n_in; (void)out_size;
}